// round 5
// baseline (speedup 1.0000x reference)
#include <cuda_runtime.h>

// QLinear int4-group dequant GEMM. M=32, K=4096, N=11008, group=32.
// MT=8 x NT=8 register tile per lane, fma.rn.f32x2, k-split over 16 partials.

#define MM 32
#define KK 4096
#define NN 11008
#define KC 64
#define BN 64
#define KSPLIT 8
#define KSPAN (KK / KSPLIT)     // 512
#define THREADS 64

typedef unsigned long long ull;

__device__ float g_xT[KK * MM];                // x transposed [k][m]
__device__ float g_part[2 * KSPLIT * MM * NN]; // 16 k-partials (22.5MB)

__global__ __launch_bounds__(256)
void transpose_x(const float* __restrict__ x) {
    __shared__ float t[32][33];
    const int k0 = blockIdx.x * 32;
    const int c = threadIdx.x & 31;
    const int r = threadIdx.x >> 5;          // 0..7
    #pragma unroll
    for (int i = 0; i < 4; i++) {            // coalesced reads along k
        int m = r + i * 8;
        t[c][m] = x[(size_t)m * KK + k0 + c];
    }
    __syncthreads();
    #pragma unroll
    for (int i = 0; i < 4; i++) {            // coalesced writes along m
        int kk = r + i * 8;
        g_xT[(size_t)(k0 + kk) * MM + c] = t[kk][c];
    }
}

__device__ __forceinline__ ull ffma2(ull a, ull b, ull c) {
    ull d;
    asm("fma.rn.f32x2 %0, %1, %2, %3;" : "=l"(d) : "l"(a), "l"(b), "l"(c));
    return d;
}
__device__ __forceinline__ ull splat2(float w) {
    ull p;
    asm("mov.b64 %0, {%1, %1};" : "=l"(p) : "f"(w));
    return p;
}
__device__ __forceinline__ float dq1(int q, float s, float z) {
    float f = __int_as_float(q | 0x4B000000);   // 2^23 + q
    float t = f - 8388616.0f;                   // exact: q - 8
    return __fmaf_rn(t, s, z);
}
__device__ __forceinline__ float lo2(ull a) { return __uint_as_float((unsigned)a); }
__device__ __forceinline__ float hi2(ull a) { return __uint_as_float((unsigned)(a >> 32)); }

__global__ __launch_bounds__(THREADS)
void qlinear4(const int* __restrict__ w, const float* __restrict__ sz)
{
    __shared__ __align__(16) float xs[KC * MM];    // [kk][m]  8KB
    __shared__ __align__(16) float wq[KC][BN];     // [kk][n] 16KB

    const int tid  = threadIdx.x;
    const int lane = tid & 31;
    const int wid  = tid >> 5;
    const int nt   = blockIdx.x >> 3;
    const int kq   = blockIdx.x & 7;
    const int nb   = nt * BN;
    const int kbeg = kq * KSPAN;

    const int mg = lane & 3;   const int m0 = mg * 8;
    const int ng = lane >> 2;  const int n0 = ng * 8;

    ull acc[4][8];
    #pragma unroll
    for (int mi = 0; mi < 4; mi++)
        #pragma unroll
        for (int nj = 0; nj < 8; nj++) acc[mi][nj] = 0ull;

    const int* wrow = w + (size_t)(nb + tid) * KK + kbeg;
    const float2* szp = (const float2*)sz;

    for (int c = 0; c < KSPAN / KC; c++) {         // 8 chunks
        const int k0 = kbeg + c * KC;

        // ---- stage x chunk ----
        const float4* xsrc = (const float4*)(g_xT + (size_t)k0 * MM);
        #pragma unroll
        for (int i = 0; i < (KC * MM / 4) / THREADS; i++)    // 8 iters
            ((float4*)xs)[i * THREADS + tid] = xsrc[i * THREADS + tid];

        // ---- dequant: thread owns column n = nb+tid, kk = 0..63 ----
        {
            const int g0 = k0 >> 5;
            float2 s0 = szp[(size_t)g0 * NN + nb + tid];
            float2 s1 = szp[(size_t)(g0 + 1) * NN + nb + tid];
            #pragma unroll
            for (int j = 0; j < 16; j++) {
                int4 q = *(const int4*)(wrow + c * KC + j * 4);
                float s = (j < 8) ? s0.x : s1.x;
                float z = (j < 8) ? s0.y : s1.y;
                wq[j * 4 + 0][tid] = dq1(q.x, s, z);
                wq[j * 4 + 1][tid] = dq1(q.y, s, z);
                wq[j * 4 + 2][tid] = dq1(q.z, s, z);
                wq[j * 4 + 3][tid] = dq1(q.w, s, z);
            }
        }
        __syncthreads();

        // ---- compute: warp wid handles kk = wid*32 .. +31 ----
        const int kk0 = wid * 32;
        #pragma unroll 4
        for (int kk = kk0; kk < kk0 + 32; kk++) {
            ull xp[4];
            {
                double2 da = *(const double2*)(xs + kk * MM + m0);
                double2 db = *(const double2*)(xs + kk * MM + m0 + 4);
                xp[0] = __double_as_longlong(da.x);
                xp[1] = __double_as_longlong(da.y);
                xp[2] = __double_as_longlong(db.x);
                xp[3] = __double_as_longlong(db.y);
            }
            float wv[8];
            *(float4*)(wv)     = *(const float4*)(&wq[kk][n0]);
            *(float4*)(wv + 4) = *(const float4*)(&wq[kk][n0 + 4]);
            ull ws[8];
            #pragma unroll
            for (int nj = 0; nj < 8; nj++) ws[nj] = splat2(wv[nj]);
            #pragma unroll
            for (int mi = 0; mi < 4; mi++)
                #pragma unroll
                for (int nj = 0; nj < 8; nj++)
                    acc[mi][nj] = ffma2(xp[mi], ws[nj], acc[mi][nj]);
        }
        __syncthreads();
    }

    // ---- write this (block,warp)'s k-partial: slot p = kq*2 + wid ----
    float* pbase = g_part + (size_t)(kq * 2 + wid) * (MM * NN);
    #pragma unroll
    for (int mi = 0; mi < 4; mi++) {
        int me = m0 + 2 * mi;
        float4 e0 = make_float4(lo2(acc[mi][0]), lo2(acc[mi][1]), lo2(acc[mi][2]), lo2(acc[mi][3]));
        float4 e1 = make_float4(lo2(acc[mi][4]), lo2(acc[mi][5]), lo2(acc[mi][6]), lo2(acc[mi][7]));
        float4 o0 = make_float4(hi2(acc[mi][0]), hi2(acc[mi][1]), hi2(acc[mi][2]), hi2(acc[mi][3]));
        float4 o1 = make_float4(hi2(acc[mi][4]), hi2(acc[mi][5]), hi2(acc[mi][6]), hi2(acc[mi][7]));
        *(float4*)(pbase + (size_t)me * NN + nb + n0)           = e0;
        *(float4*)(pbase + (size_t)me * NN + nb + n0 + 4)       = e1;
        *(float4*)(pbase + (size_t)(me + 1) * NN + nb + n0)     = o0;
        *(float4*)(pbase + (size_t)(me + 1) * NN + nb + n0 + 4) = o1;
    }
}

__global__ void reduce_out(const float* __restrict__ bias, float* __restrict__ out)
{
    int i = blockIdx.x * blockDim.x + threadIdx.x;     // float4 index
    const int TOT4 = MM * NN / 4;                       // 88064
    if (i < TOT4) {
        float4 a = make_float4(0.f, 0.f, 0.f, 0.f);
        #pragma unroll
        for (int p = 0; p < 2 * KSPLIT; p++) {
            float4 v = ((const float4*)g_part)[(size_t)p * TOT4 + i];
            a.x += v.x; a.y += v.y; a.z += v.z; a.w += v.w;
        }
        int n4 = i % (NN / 4);
        float4 b = ((const float4*)bias)[n4];
        a.x += b.x; a.y += b.y; a.z += b.z; a.w += b.w;
        ((float4*)out)[i] = a;
    }
}

extern "C" void kernel_launch(void* const* d_in, const int* in_sizes, int n_in,
                              void* d_out, int out_size) {
    const float* x    = (const float*)d_in[0];
    const int*   wgt  = (const int*)d_in[1];
    const float* sz   = (const float*)d_in[2];
    const float* bias = (const float*)d_in[3];
    float* out = (float*)d_out;
    transpose_x<<<KK / 32, 256>>>(x);
    qlinear4<<<(NN / BN) * KSPLIT, THREADS>>>(wgt, sz);
    reduce_out<<<(MM * NN / 4 + 127) / 128, 128>>>(bias, out);
}

// round 7
// speedup vs baseline: 2.2618x; 2.2618x over previous
#include <cuda_runtime.h>
#include <cuda_bf16.h>
#include <cstdint>

// QLinear int4 dequant GEMM via mma.sync bf16 split-precision (sm_80 baseline ISA).
// D[n_out, tok] = W[n,k] @ X^T;  A = W row-major, B = x natural [tok][k] (col-major B).
// 3 products per step: Ah*Bh + Ah*Bl + Al*Bh  (split err ~2^-16).

#define MM 32
#define KK 4096
#define NN 11008
#define BN 128
#define KSPLIT 8
#define KSPAN (KK / KSPLIT)    // 512
#define KC 128
#define THREADS 256
#define XS 272                 // x smem row stride (bytes): 256 data + 16 pad
#define RS 132                 // res row stride (floats)

__device__ __nv_bfloat16 g_xh[MM * KK];
__device__ __nv_bfloat16 g_xl[MM * KK];
__device__ float g_part[KSPLIT][MM * NN];

__global__ void split_x(const float* __restrict__ x) {
    int i = blockIdx.x * blockDim.x + threadIdx.x;
    if (i < MM * KK) {
        float f = x[i];
        __nv_bfloat16 h = __float2bfloat16(f);
        g_xh[i] = h;
        g_xl[i] = __float2bfloat16(f - __bfloat162float(h));
    }
}

__device__ __forceinline__ float dq1(int q, float s, float z) {
    float f = __int_as_float(q | 0x4B000000);   // 2^23 + q
    float t = f - 8388616.0f;                   // exact (Sterbenz): q - 8
    return __fmaf_rn(t, s, z);
}

// dequant an int2 (k-even, k-odd) pair -> packed bf16x2 hi + residual lo
__device__ __forceinline__ void dqpair(int2 q, float2 szv, uint32_t& hi, uint32_t& lo) {
    float s = szv.x, z = szv.y;
    float w0 = dq1(q.x, s, z);
    float w1 = dq1(q.y, s, z);
    uint32_t h;
    asm("cvt.rn.bf16x2.f32 %0, %1, %2;" : "=r"(h) : "f"(w1), "f"(w0)); // upper=w1, lower=w0
    float h0 = __uint_as_float(h << 16);
    float h1 = __uint_as_float(h & 0xFFFF0000u);
    float l0 = w0 - h0;
    float l1 = w1 - h1;
    uint32_t l;
    asm("cvt.rn.bf16x2.f32 %0, %1, %2;" : "=r"(l) : "f"(l1), "f"(l0));
    hi = h; lo = l;
}

__device__ __forceinline__ void mma16816(float* d, const uint32_t* a, uint32_t b0, uint32_t b1) {
    asm volatile(
        "mma.sync.aligned.m16n8k16.row.col.f32.bf16.bf16.f32 "
        "{%0,%1,%2,%3}, {%4,%5,%6,%7}, {%8,%9}, {%0,%1,%2,%3};"
        : "+f"(d[0]), "+f"(d[1]), "+f"(d[2]), "+f"(d[3])
        : "r"(a[0]), "r"(a[1]), "r"(a[2]), "r"(a[3]), "r"(b0), "r"(b1));
}

__global__ __launch_bounds__(THREADS)
void qlinear_mma(const int* __restrict__ w, const float* __restrict__ sz)
{
    __shared__ union {
        struct { char hi[MM * XS]; char lo[MM * XS]; } x;   // 17408 B
        float res[MM][RS];                                   // 16896 B
    } sm;

    const int tid  = threadIdx.x;
    const int lane = tid & 31;
    const int wid  = tid >> 5;
    const int nb   = blockIdx.x * BN;
    const int kq   = blockIdx.y;
    const int kbeg = kq * KSPAN;
    const int g4   = lane >> 2;   // 0..7
    const int l4   = lane & 3;    // 0..3

    // this thread's two A rows (n_out)
    const int r0 = nb + wid * 16 + g4;
    const int* wp0 = w + (size_t)r0 * KK + kbeg;
    const int* wp1 = wp0 + (size_t)8 * KK;
    const float2* szp = (const float2*)sz;

    float d[4][4];   // [tok-group][frag]
    #pragma unroll
    for (int tg = 0; tg < 4; tg++)
        #pragma unroll
        for (int j = 0; j < 4; j++) d[tg][j] = 0.f;

    for (int kc = 0; kc < KSPAN; kc += KC) {
        __syncthreads();   // previous chunk fully consumed
        // ---- stage x chunk (hi/lo), 16 KB total ----
        #pragma unroll
        for (int i = 0; i < 2; i++) {
            int idx = tid + i * THREADS;          // 0..511
            int tok = idx >> 4, seg = idx & 15;
            size_t s = (size_t)tok * KK + kbeg + kc + seg * 8;
            *(uint4*)(sm.x.hi + tok * XS + seg * 16) = *(const uint4*)(g_xh + s);
            *(uint4*)(sm.x.lo + tok * XS + seg * 16) = *(const uint4*)(g_xl + s);
        }
        // ---- scales for this chunk's 4 groups, rows r0 / r0+8 ----
        float2 sc0[4], sc1[4];
        {
            int gb = (kbeg + kc) >> 5;
            #pragma unroll
            for (int g = 0; g < 4; g++) {
                sc0[g] = szp[(size_t)(gb + g) * NN + r0];
                sc1[g] = szp[(size_t)(gb + g) * NN + r0 + 8];
            }
        }
        __syncthreads();

        #pragma unroll
        for (int st = 0; st < 8; st++) {          // k16 steps in chunk
            const int koff = kc + st * 16 + l4 * 2;
            int2 q0 = *(const int2*)(wp0 + koff);
            int2 q1 = *(const int2*)(wp1 + koff);
            int2 q2 = *(const int2*)(wp0 + koff + 8);
            int2 q3 = *(const int2*)(wp1 + koff + 8);
            float2 s0 = sc0[st >> 1];
            float2 s1 = sc1[st >> 1];

            uint32_t ah[4], al[4];
            dqpair(q0, s0, ah[0], al[0]);   // (r0,   k 0..7)
            dqpair(q1, s1, ah[1], al[1]);   // (r0+8, k 0..7)
            dqpair(q2, s0, ah[2], al[2]);   // (r0,   k 8..15)
            dqpair(q3, s1, ah[3], al[3]);   // (r0+8, k 8..15)

            #pragma unroll
            for (int tg = 0; tg < 4; tg++) {
                int base = (tg * 8 + g4) * XS + st * 32 + l4 * 4;
                uint32_t bh0 = *(const uint32_t*)(sm.x.hi + base);
                uint32_t bh1 = *(const uint32_t*)(sm.x.hi + base + 16);
                uint32_t bl0 = *(const uint32_t*)(sm.x.lo + base);
                uint32_t bl1 = *(const uint32_t*)(sm.x.lo + base + 16);
                mma16816(d[tg], ah, bh0, bh1);
                mma16816(d[tg], ah, bl0, bl1);
                mma16816(d[tg], al, bh0, bh1);
            }
        }
    }

    // ---- epilogue: stage D to smem, then coalesced partial store ----
    __syncthreads();
    #pragma unroll
    for (int tg = 0; tg < 4; tg++) {
        int tok = tg * 8 + l4 * 2;
        int nl  = wid * 16 + g4;
        sm.res[tok][nl]         = d[tg][0];
        sm.res[tok + 1][nl]     = d[tg][1];
        sm.res[tok][nl + 8]     = d[tg][2];
        sm.res[tok + 1][nl + 8] = d[tg][3];
    }
    __syncthreads();
    float* pb = g_part[kq];
    #pragma unroll
    for (int i = 0; i < 4; i++) {
        int idx = tid + i * THREADS;              // 0..1023 float4s
        int tok = idx >> 5, seg = idx & 31;
        float4 v = *(const float4*)(&sm.res[tok][seg * 4]);
        *(float4*)(pb + (size_t)tok * NN + nb + seg * 4) = v;
    }
}

__global__ void reduce_out(const float* __restrict__ bias, float* __restrict__ out)
{
    int i = blockIdx.x * blockDim.x + threadIdx.x;   // float4 index
    const int TOT4 = MM * NN / 4;
    if (i < TOT4) {
        float4 a = make_float4(0.f, 0.f, 0.f, 0.f);
        #pragma unroll
        for (int p = 0; p < KSPLIT; p++) {
            float4 v = ((const float4*)g_part[p])[i];
            a.x += v.x; a.y += v.y; a.z += v.z; a.w += v.w;
        }
        float4 b = ((const float4*)bias)[i % (NN / 4)];
        a.x += b.x; a.y += b.y; a.z += b.z; a.w += b.w;
        ((float4*)out)[i] = a;
    }
}

extern "C" void kernel_launch(void* const* d_in, const int* in_sizes, int n_in,
                              void* d_out, int out_size) {
    const float* x    = (const float*)d_in[0];
    const int*   wgt  = (const int*)d_in[1];
    const float* sz   = (const float*)d_in[2];
    const float* bias = (const float*)d_in[3];
    float* out = (float*)d_out;
    split_x<<<(MM * KK + 255) / 256, 256>>>(x);
    qlinear_mma<<<dim3(NN / BN, KSPLIT), THREADS>>>(wgt, sz);
    reduce_out<<<(MM * NN / 4 + 127) / 128, 128>>>(bias, out);
}